// round 5
// baseline (speedup 1.0000x reference)
#include <cuda_runtime.h>
#include <math.h>
#define G 128
#define NT 256
#define TT 4800
typedef unsigned long long u64;
typedef unsigned int u32;

#define OFF_G1I 0
#define OFF_G1H 6144
#define OFF_G2I 12288
#define OFF_G2H 18816
#define OFF_F1W 24960
#define OFF_F2W 27136
#define OFF_F3W 29312
#define OFF_W0  31360
#define OFF_G1B 31872
#define OFF_G2B 31888
#define OFF_F1B 31904
#define OFF_F2B 31908
#define OFF_F3B 31912
#define OFF_ACTA 31916
#define OFF_ACTH 34092
#define OFF_STAG 36140
#define OFF_CND  36236
#define OFF_SAMP 36268
#define SMEMF 36272
#define SMEM_BYTES (SMEMF*4)

struct __align__(256) R32 { float d[32]; u32 pad[31]; u32 ep; };
struct __align__(128) R16 { float d[16]; u32 pad[15]; u32 ep; };
struct __align__(128) RC  { u64 k[4];  u32 pad[23]; u32 ep; };
__device__ R32 RG1[2][G], RG2[2][G];
__device__ R16 RF1[G], RF2[G];
__device__ RC  RFC[G];
__device__ float g_pre[TT*512*4];
__device__ u32 g_fl[G*32];

__device__ __forceinline__ u32 ld_acq(const u32* p){
    u32 v; asm volatile("ld.acquire.gpu.global.b32 %0,[%1];":"=r"(v):"l"(p):"memory"); return v;
}
__device__ __forceinline__ void st_rel(u32* p, u32 v){
    asm volatile("st.release.gpu.global.b32 [%0],%1;"::"l"(p),"r"(v):"memory");
}
__device__ __forceinline__ void gbar(int bx, u32& ep){
    __syncthreads();
    ep++;
    if(threadIdx.x==0) st_rel(&g_fl[bx*32], ep);
    if(threadIdx.x<G){ const u32* f=&g_fl[threadIdx.x*32]; while((int)(ld_acq(f)-ep)<0){} }
    __syncthreads();
}

__device__ __forceinline__ void gru_stage(float* sm,int offI,int offH,int offB,int Kin,int n0,R32* rec,u32 tgt){
    const int tid=threadIdx.x,w=tid>>5,lane=tid&31,n=w>>1,half=w&1;
    const float4* A=(const float4*)(sm+(half?OFF_ACTH:OFF_ACTA));
    const int K=half?512:Kin;
    const float* W=sm+(half?offH:offI)+n*3*K;
    float acc[3][4]={};
    #pragma unroll 2
    for(int k=lane;k<K;k+=32){
        float4 a=A[k];
        #pragma unroll
        for(int g=0;g<3;g++){float wv=W[g*K+k];
            acc[g][0]=fmaf(wv,a.x,acc[g][0]);acc[g][1]=fmaf(wv,a.y,acc[g][1]);
            acc[g][2]=fmaf(wv,a.z,acc[g][2]);acc[g][3]=fmaf(wv,a.w,acc[g][3]);}
    }
    #pragma unroll
    for(int o=16;o;o>>=1)
        #pragma unroll
        for(int g=0;g<3;g++)
            #pragma unroll
            for(int b=0;b<4;b++) acc[g][b]+=__shfl_xor_sync(~0u,acc[g][b],o);
    if(!lane)
        #pragma unroll
        for(int g=0;g<3;g++)
            #pragma unroll
            for(int b=0;b<4;b++) sm[OFF_STAG+n*24+half*12+g*4+b]=acc[g][b];
    __syncthreads();
    if(tid<16){
        int nn=tid>>2,b=tid&3; const float*S=sm+OFF_STAG+nn*24; const float*B=sm+offB+nn*4;
        float r=1.f/(1.f+expf(-(S[b]+S[12+b]+B[0])));
        float z=1.f/(1.f+expf(-(S[4+b]+S[16+b]+B[1])));
        float nv=tanhf(S[8+b]+B[2]+r*(S[20+b]+B[3]));
        float hv=(1.f-z)*nv+z*sm[OFF_ACTH+(n0+nn)*4+b];
        rec->d[16+nn*4+b]=hv;
        rec->d[nn*4+b]=sm[OFF_ACTA+(n0+nn)*4+b]+hv;
    }
    __syncthreads();
    if(!tid) st_rel(&rec->ep,tgt);
}

__device__ __forceinline__ void fc_stage(float* sm,int offW,int offB,int K,float* dd,bool relu){
    const int tid=threadIdx.x,w=tid>>5,lane=tid&31,n=w>>1,kh=w&1,Kh=K>>1;
    const float4* A=(const float4*)(sm+OFF_ACTA);
    const float* W=sm+offW+n*K;
    float a0=0,a1=0,a2=0,a3=0;
    #pragma unroll 2
    for(int k=kh*Kh+lane;k<kh*Kh+Kh;k+=32){float4 a=A[k];float wv=W[k];
        a0=fmaf(wv,a.x,a0);a1=fmaf(wv,a.y,a1);a2=fmaf(wv,a.z,a2);a3=fmaf(wv,a.w,a3);}
    #pragma unroll
    for(int o=16;o;o>>=1){
        a0+=__shfl_xor_sync(~0u,a0,o);a1+=__shfl_xor_sync(~0u,a1,o);
        a2+=__shfl_xor_sync(~0u,a2,o);a3+=__shfl_xor_sync(~0u,a3,o);}
    if(!lane){float*S=sm+OFF_STAG+w*4;S[0]=a0;S[1]=a1;S[2]=a2;S[3]=a3;}
    __syncthreads();
    if(tid<16){int nn=tid>>2,b=tid&3;
        float v=sm[OFF_STAG+nn*8+b]+sm[OFF_STAG+nn*8+4+b]+sm[offB+nn];
        if(relu)v=fmaxf(v,0.f);
        dd[nn*4+b]=v;}
    __syncthreads();
}

extern "C" __global__ void __launch_bounds__(NT,1) wavernn_kernel(
    const float* __restrict__ mel,   const float* __restrict__ aux,
    const float* __restrict__ WI,    const float* __restrict__ bI,
    const float* __restrict__ g1wih, const float* __restrict__ g1whh,
    const float* __restrict__ g1bih, const float* __restrict__ g1bhh,
    const float* __restrict__ g2wih, const float* __restrict__ g2whh,
    const float* __restrict__ g2bih, const float* __restrict__ g2bhh,
    const float* __restrict__ f1w,   const float* __restrict__ f1b,
    const float* __restrict__ f2w,   const float* __restrict__ f2b,
    const float* __restrict__ f3w,   const float* __restrict__ f3b,
    float* __restrict__ out)
{
    extern __shared__ float sm[];
    const int tid=threadIdx.x, bx=blockIdx.x, n0=bx*4;
    const u32 eb=ld_acq(&RFC[bx].ep);
    u32 fep=ld_acq(&g_fl[bx*32]);

    // precompute pre[t] = b_I + W_I[:,1:]*[mel,aux0] for this CTA's t-chunk
    {
        int t0=bx*TT/G, t1=(bx+1)*TT/G;
        for(int p=0;p<4;p++){
            for(int i=tid;i<128*112;i+=NT){int j=i/112,c=i-j*112;sm[j*112+c]=__ldg(&WI[(p*128+j)*113+1+c]);}
            __syncthreads();
            int jl=tid>>1,bh=tid&1,j=p*128+jl;
            float bias=__ldg(&bI[j]);
            const float* Wr=sm+jl*112;
            for(int t=t0;t<t1;t++){
                float a0=bias,a1=bias;
                const float*m0=mel+(bh*2*TT+t)*80,*m1=mel+((bh*2+1)*TT+t)*80;
                const float*x0=aux+(bh*2*TT+t)*128,*x1=aux+((bh*2+1)*TT+t)*128;
                #pragma unroll 8
                for(int c=0;c<80;c++){float wv=Wr[c];a0=fmaf(wv,__ldg(m0+c),a0);a1=fmaf(wv,__ldg(m1+c),a1);}
                #pragma unroll 8
                for(int c=0;c<32;c++){float wv=Wr[80+c];a0=fmaf(wv,__ldg(x0+c),a0);a1=fmaf(wv,__ldg(x1+c),a1);}
                g_pre[((size_t)t*512+j)*4+bh*2]=a0; g_pre[((size_t)t*512+j)*4+bh*2+1]=a1;
            }
            __syncthreads();
        }
    }
    // weights into SMEM
    for(int i=tid;i<6144;i+=NT){int j=i/1536,r=i-j*1536,g=r>>9,k=r&511;
        sm[OFF_G1I+i]=__ldg(&g1wih[(g*512+n0+j)*512+k]);
        sm[OFF_G1H+i]=__ldg(&g1whh[(g*512+n0+j)*512+k]);
        sm[OFF_G2H+i]=__ldg(&g2whh[(g*512+n0+j)*512+k]);}
    for(int i=tid;i<6528;i+=NT){int j=i/1632,r=i-j*1632,g=r/544,k=r-g*544;
        sm[OFF_G2I+i]=__ldg(&g2wih[(g*512+n0+j)*544+k]);}
    for(int i=tid;i<2176;i+=NT){int j=i/544,k=i-j*544;
        sm[OFF_F1W+i]=__ldg(&f1w[(n0+j)*544+k]);sm[OFF_F2W+i]=__ldg(&f2w[(n0+j)*544+k]);}
    for(int i=tid;i<2048;i+=NT) sm[OFF_F3W+i]=__ldg(&f3w[(n0+(i>>9))*512+(i&511)]);
    for(int i=tid;i<512;i+=NT)  sm[OFF_W0+i]=__ldg(&WI[i*113]);
    if(tid<16){
        int nn=tid>>2,c=tid&3,n=n0+nn; float v1,v2;
        if(c==0){v1=g1bih[n]+g1bhh[n];v2=g2bih[n]+g2bhh[n];}
        else if(c==1){v1=g1bih[512+n]+g1bhh[512+n];v2=g2bih[512+n]+g2bhh[512+n];}
        else if(c==2){v1=g1bih[1024+n];v2=g2bih[1024+n];}
        else{v1=g1bhh[1024+n];v2=g2bhh[1024+n];}
        sm[OFF_G1B+tid]=v1; sm[OFF_G2B+tid]=v2;
    }
    if(tid<4){sm[OFF_F1B+tid]=f1b[n0+tid];sm[OFF_F2B+tid]=f2b[n0+tid];sm[OFF_F3B+tid]=f3b[n0+tid];}
    gbar(bx,fep);

    float* outL=out+4*TT;
    for(int t=0;t<TT;t++){
        const int pa=t&1, pb=pa^1;
        const u32 e=eb+(u32)t*5u;
        // P1: argmax(prev) + h1 + local x = pre + w0*s ; GRU1
        {
            const float4* gp=(const float4*)g_pre+((size_t)t*512+2*tid);
            float4 p0=__ldcg(gp), p1=__ldcg(gp+1);
            if(tid<128){
                float4* Dh=(float4*)(sm+OFF_ACTH)+tid*4;
                if(t){
                    const RC* r=&RFC[tid];
                    while((int)(ld_acq(&r->ep)-e)<0){}
                    u64 k0=__ldcg(&r->k[0]),k1=__ldcg(&r->k[1]),k2=__ldcg(&r->k[2]),k3=__ldcg(&r->k[3]);
                    const float4* h=(const float4*)RG1[pb][tid].d+4;
                    Dh[0]=__ldcg(h);Dh[1]=__ldcg(h+1);Dh[2]=__ldcg(h+2);Dh[3]=__ldcg(h+3);
                    #pragma unroll
                    for(int o=16;o;o>>=1){u64 v;
                        v=__shfl_xor_sync(~0u,k0,o);if(v>k0)k0=v;
                        v=__shfl_xor_sync(~0u,k1,o);if(v>k1)k1=v;
                        v=__shfl_xor_sync(~0u,k2,o);if(v>k2)k2=v;
                        v=__shfl_xor_sync(~0u,k3,o);if(v>k3)k3=v;}
                    if(!(tid&31)){u64*C=(u64*)(sm+OFF_CND)+(tid>>5)*4;C[0]=k0;C[1]=k1;C[2]=k2;C[3]=k3;}
                }else{
                    float4 z=make_float4(0,0,0,0);Dh[0]=z;Dh[1]=z;Dh[2]=z;Dh[3]=z;
                }
            }
            __syncthreads();
            if(tid<4){
                float s=0.f;
                if(t){u64*C=(u64*)(sm+OFF_CND);u64 m=C[tid];
                    #pragma unroll
                    for(int w=1;w<4;w++){u64 v=C[w*4+tid];if(v>m)m=v;}
                    int idx=511-(int)(m&0xffffffffull);
                    s=2.f*(float)idx/511.f-1.f;
                    if(bx==0) out[tid*TT+(t-1)]=s;
                }
                sm[OFF_SAMP+tid]=s;
            }
            __syncthreads();
            {
                float4 sv=*(const float4*)(sm+OFF_SAMP);
                float wa=sm[OFF_W0+2*tid], wb=sm[OFF_W0+2*tid+1];
                float4 x0,x1;
                x0.x=fmaf(wa,sv.x,p0.x);x0.y=fmaf(wa,sv.y,p0.y);x0.z=fmaf(wa,sv.z,p0.z);x0.w=fmaf(wa,sv.w,p0.w);
                x1.x=fmaf(wb,sv.x,p1.x);x1.y=fmaf(wb,sv.y,p1.y);x1.z=fmaf(wb,sv.z,p1.z);x1.w=fmaf(wb,sv.w,p1.w);
                float4* Aa=(float4*)(sm+OFF_ACTA); Aa[2*tid]=x0; Aa[2*tid+1]=x1;
            }
            __syncthreads();
            gru_stage(sm,OFF_G1I,OFF_G1H,OFF_G1B,512,n0,&RG1[pa][bx],e+1);
        }
        // P2: GRU2
        if(tid<128){
            const R32* r=&RG1[pa][tid];
            while((int)(ld_acq(&r->ep)-(e+1))<0){}
            float4* Da=(float4*)(sm+OFF_ACTA)+tid*4;
            const float4* s=(const float4*)r->d;
            Da[0]=__ldcg(s);Da[1]=__ldcg(s+1);Da[2]=__ldcg(s+2);Da[3]=__ldcg(s+3);
            float4* Dh=(float4*)(sm+OFF_ACTH)+tid*4;
            if(t){const float4* h=(const float4*)RG2[pb][tid].d+4;
                Dh[0]=__ldcg(h);Dh[1]=__ldcg(h+1);Dh[2]=__ldcg(h+2);Dh[3]=__ldcg(h+3);}
            else{float4 z=make_float4(0,0,0,0);Dh[0]=z;Dh[1]=z;Dh[2]=z;Dh[3]=z;}
        }else if(tid>=224){int c=tid-224;
            ((float4*)(sm+OFF_ACTA))[512+c]=make_float4(aux[(0*TT+t)*128+32+c],aux[(1*TT+t)*128+32+c],aux[(2*TT+t)*128+32+c],aux[(3*TT+t)*128+32+c]);}
        __syncthreads();
        gru_stage(sm,OFF_G2I,OFF_G2H,OFF_G2B,544,n0,&RG2[pa][bx],e+2);
        // P3: fc1
        if(tid<128){
            const R32* r=&RG2[pa][tid];
            while((int)(ld_acq(&r->ep)-(e+2))<0){}
            float4* Da=(float4*)(sm+OFF_ACTA)+tid*4;
            const float4* s=(const float4*)r->d;
            Da[0]=__ldcg(s);Da[1]=__ldcg(s+1);Da[2]=__ldcg(s+2);Da[3]=__ldcg(s+3);
        }else if(tid>=224){int c=tid-224;
            ((float4*)(sm+OFF_ACTA))[512+c]=make_float4(aux[(0*TT+t)*128+64+c],aux[(1*TT+t)*128+64+c],aux[(2*TT+t)*128+64+c],aux[(3*TT+t)*128+64+c]);}
        __syncthreads();
        fc_stage(sm,OFF_F1W,OFF_F1B,544,RF1[bx].d,true);
        if(!tid) st_rel(&RF1[bx].ep,e+3);
        // P4: fc2
        if(tid<128){
            const R16* r=&RF1[tid];
            while((int)(ld_acq(&r->ep)-(e+3))<0){}
            float4* Da=(float4*)(sm+OFF_ACTA)+tid*4;
            const float4* s=(const float4*)r->d;
            Da[0]=__ldcg(s);Da[1]=__ldcg(s+1);Da[2]=__ldcg(s+2);Da[3]=__ldcg(s+3);
        }else if(tid>=224){int c=tid-224;
            ((float4*)(sm+OFF_ACTA))[512+c]=make_float4(aux[(0*TT+t)*128+96+c],aux[(1*TT+t)*128+96+c],aux[(2*TT+t)*128+96+c],aux[(3*TT+t)*128+96+c]);}
        __syncthreads();
        fc_stage(sm,OFF_F2W,OFF_F2B,544,RF2[bx].d,true);
        if(!tid) st_rel(&RF2[bx].ep,e+4);
        // P5: fc3 + keys
        if(tid<128){
            const R16* r=&RF2[tid];
            while((int)(ld_acq(&r->ep)-(e+4))<0){}
            float4* Da=(float4*)(sm+OFF_ACTA)+tid*4;
            const float4* s=(const float4*)r->d;
            Da[0]=__ldcg(s);Da[1]=__ldcg(s+1);Da[2]=__ldcg(s+2);Da[3]=__ldcg(s+3);
        }
        __syncthreads();
        {
            const int w=tid>>5,lane=tid&31,n=w>>1,kh=w&1;
            const float4* A=(const float4*)(sm+OFF_ACTA);
            const float* W=sm+OFF_F3W+n*512;
            float a0=0,a1=0,a2=0,a3=0;
            #pragma unroll 2
            for(int k=kh*256+lane;k<kh*256+256;k+=32){float4 a=A[k];float wv=W[k];
                a0=fmaf(wv,a.x,a0);a1=fmaf(wv,a.y,a1);a2=fmaf(wv,a.z,a2);a3=fmaf(wv,a.w,a3);}
            #pragma unroll
            for(int o=16;o;o>>=1){
                a0+=__shfl_xor_sync(~0u,a0,o);a1+=__shfl_xor_sync(~0u,a1,o);
                a2+=__shfl_xor_sync(~0u,a2,o);a3+=__shfl_xor_sync(~0u,a3,o);}
            if(!lane){float*S=sm+OFF_STAG+w*4;S[0]=a0;S[1]=a1;S[2]=a2;S[3]=a3;}
            __syncthreads();
            if(tid<16){
                int nn=tid>>2,b=tid&3;
                float v=sm[OFF_STAG+nn*8+b]+sm[OFF_STAG+nn*8+4+b]+sm[OFF_F3B+nn];
                outL[((size_t)b*TT+t)*512+n0+nn]=v;
                u32 u=__float_as_uint(v); u=(u&0x80000000u)?~u:(u|0x80000000u);
                u64 key=((u64)u<<32)|(u32)(511-(n0+nn));
                u64 v1=__shfl_xor_sync(0xffffu,key,4); if(v1>key)key=v1;
                u64 v2=__shfl_xor_sync(0xffffu,key,8); if(v2>key)key=v2;
                if(tid<4) RFC[bx].k[tid]=key;
            }
            __syncthreads();
            if(!tid) st_rel(&RFC[bx].ep,e+5);
        }
    }
    // tail: last sample (t = TT-1)
    if(bx==0){
        const u32 tgt=eb+(u32)TT*5u;
        if(tid<128){
            const RC* r=&RFC[tid];
            while((int)(ld_acq(&r->ep)-tgt)<0){}
            u64 k0=__ldcg(&r->k[0]),k1=__ldcg(&r->k[1]),k2=__ldcg(&r->k[2]),k3=__ldcg(&r->k[3]);
            #pragma unroll
            for(int o=16;o;o>>=1){u64 v;
                v=__shfl_xor_sync(~0u,k0,o);if(v>k0)k0=v;
                v=__shfl_xor_sync(~0u,k1,o);if(v>k1)k1=v;
                v=__shfl_xor_sync(~0u,k2,o);if(v>k2)k2=v;
                v=__shfl_xor_sync(~0u,k3,o);if(v>k3)k3=v;}
            if(!(tid&31)){u64*C=(u64*)(sm+OFF_CND)+(tid>>5)*4;C[0]=k0;C[1]=k1;C[2]=k2;C[3]=k3;}
        }
        __syncthreads();
        if(tid<4){
            u64*C=(u64*)(sm+OFF_CND); u64 m=C[tid];
            #pragma unroll
            for(int w=1;w<4;w++){u64 v=C[w*4+tid];if(v>m)m=v;}
            int idx=511-(int)(m&0xffffffffull);
            out[tid*TT+TT-1]=2.f*(float)idx/511.f-1.f;
        }
    }
}

extern "C" void kernel_launch(void* const* d_in, const int* in_sizes, int n_in,
                              void* d_out, int out_size){
    (void)in_sizes;(void)n_in;(void)out_size;
    cudaFuncSetAttribute(wavernn_kernel, cudaFuncAttributeMaxDynamicSharedMemorySize, SMEM_BYTES);
    wavernn_kernel<<<G,NT,SMEM_BYTES>>>(
        (const float*)d_in[0],(const float*)d_in[1],(const float*)d_in[2],
        (const float*)d_in[3],(const float*)d_in[4],(const float*)d_in[5],
        (const float*)d_in[6],(const float*)d_in[7],(const float*)d_in[8],
        (const float*)d_in[9],(const float*)d_in[10],(const float*)d_in[11],
        (const float*)d_in[12],(const float*)d_in[13],(const float*)d_in[14],
        (const float*)d_in[15],(const float*)d_in[16],(const float*)d_in[17],
        (float*)d_out);
}

// round 8
// speedup vs baseline: 1.3693x; 1.3693x over previous
#include <cuda_runtime.h>
#include <math.h>
#define G 128
#define NT 256
#define TT 4800
typedef unsigned long long u64;
typedef unsigned int u32;

// SMEM float offsets
#define OFF_G1I 0
#define OFF_G1H 6144
#define OFF_G2I 12288
#define OFF_G2H 18816
#define OFF_F1W 24960
#define OFF_F2W 27136
#define OFF_F3W 29312
#define OFF_W0  31360
#define OFF_G1B 31872
#define OFF_G2B 31888
#define OFF_F1B 31904
#define OFF_F2B 31908
#define OFF_F3B 31912
#define OFF_ACTA 31916
#define OFF_ACTH 34092
#define OFF_ACTH2 36140
#define OFF_AUX 38188
#define OFF_STAG 38572
#define OFF_SAMP 38668
#define SMEMF 38672
#define SMEM_BYTES (SMEMF*4)

__device__ float g_x2[2048], g_x3[2048], g_y1[2048], g_y2[2048];
__device__ float g_h1[2][2048], g_h2[2][2048];
__device__ u64 g_cand[G*4];
__device__ float g_pre[(size_t)TT*2048];
__device__ u32 g_fl[G*32];   // one 128B line per CTA; monotonic across replays

__device__ __forceinline__ u32 ld_acq(const u32* p){
    u32 v; asm volatile("ld.acquire.gpu.global.b32 %0,[%1];":"=r"(v):"l"(p):"memory"); return v;
}
__device__ __forceinline__ void st_rel(u32* p, u32 v){
    asm volatile("st.release.gpu.global.b32 [%0],%1;"::"l"(p),"r"(v):"memory");
}
__device__ __forceinline__ u64 pk2(float x){ u64 r; asm("mov.b64 %0,{%1,%1};":"=l"(r):"f"(x)); return r; }
__device__ __forceinline__ void fma2(u64& d,u64 a,u64 b){ asm("fma.rn.f32x2 %0,%1,%2,%0;":"+l"(d):"l"(a),"l"(b)); }
__device__ __forceinline__ u64 add2(u64 a,u64 b){ u64 r; asm("add.rn.f32x2 %0,%1,%2;":"=l"(r):"l"(a),"l"(b)); return r; }
__device__ __forceinline__ void unpk(u64 v,float& lo,float& hi){ asm("mov.b64 {%0,%1},%2;":"=f"(lo),"=f"(hi):"l"(v)); }
__device__ __forceinline__ void lds2(u64& a,u64& b,u32 addr){
    asm volatile("ld.shared.v2.u64 {%0,%1},[%2];":"=l"(a),"=l"(b):"r"(addr));
}

// proven flag-array grid barrier: per-CTA epoch base, monotonic across replays
#define BAR() do{ ep++; __syncthreads(); \
    if(tid==0) st_rel(&g_fl[bx*32],ep); \
    if(tid<G){ const u32* f=&g_fl[tid*32]; while((int)(ld_acq(f)-ep)<0){} } \
    __syncthreads(); }while(0)

__device__ __forceinline__ void ldx(float* dst,const float* src){
    float4* D=(float4*)dst; const float4* S=(const float4*)src;
    for(int i=threadIdx.x;i<512;i+=NT) D[i]=__ldcg(S+i);
}

// GRU stage: 8 warps = 4 neurons x {input side, hidden side}; packed batch FMAs.
__device__ __forceinline__ void gru_stage(float* sm,u32 smb,int offHH,int offI,int offH,int offB,
                                          int Kin,int n0,float* xo,float* ho){
    const int tid=threadIdx.x,w=tid>>5,lane=tid&31,n=w>>1,half=w&1;
    const int K=half?512:Kin;
    const u32 aB=smb+(u32)(half?offHH:OFF_ACTA)*4u;
    const float* W0=sm+(half?offH:offI)+n*3*K;
    const float* W1=W0+K; const float* W2=W1+K;
    u64 ac[6]={0,0,0,0,0,0};
    #pragma unroll 2
    for(int k=lane;k<K;k+=32){
        u64 a01,a23; lds2(a01,a23,aB+(u32)k*16u);
        u64 w0=pk2(W0[k]),w1=pk2(W1[k]),w2=pk2(W2[k]);
        fma2(ac[0],w0,a01); fma2(ac[1],w0,a23);
        fma2(ac[2],w1,a01); fma2(ac[3],w1,a23);
        fma2(ac[4],w2,a01); fma2(ac[5],w2,a23);
    }
    #pragma unroll
    for(int o=16;o;o>>=1)
        #pragma unroll
        for(int j=0;j<6;j++) ac[j]=add2(ac[j],__shfl_xor_sync(~0u,ac[j],o));
    if(!lane){
        float* S=sm+OFF_STAG+(n*2+half)*12;
        unpk(ac[0],S[0],S[1]); unpk(ac[1],S[2],S[3]);
        unpk(ac[2],S[4],S[5]); unpk(ac[3],S[6],S[7]);
        unpk(ac[4],S[8],S[9]); unpk(ac[5],S[10],S[11]);
    }
    __syncthreads();
    if(tid<16){
        int nn=tid>>2,b=tid&3;
        const float* Si=sm+OFF_STAG+nn*24; const float* Sh=Si+12; const float* B=sm+offB+nn*4;
        float r=1.f/(1.f+expf(-(Si[b]+Sh[b]+B[0])));
        float z=1.f/(1.f+expf(-(Si[4+b]+Sh[4+b]+B[1])));
        float nv=tanhf(Si[8+b]+B[2]+r*(Sh[8+b]+B[3]));
        float hv=(1.f-z)*nv+z*sm[offHH+(n0+nn)*4+b];
        ho[(n0+nn)*4+b]=hv;
        xo[(n0+nn)*4+b]=sm[OFF_ACTA+(n0+nn)*4+b]+hv;
    }
}

__device__ __forceinline__ void fc_stage(float* sm,u32 smb,int offW,int offB,int K,int n0,
                                         float* dd,bool relu){
    const int tid=threadIdx.x,w=tid>>5,lane=tid&31,n=w>>1,kh=w&1,Kh=K>>1;
    const u32 aB=smb+(u32)OFF_ACTA*4u;
    const float* W=sm+offW+n*K;
    u64 a01=0,a23=0;
    #pragma unroll 2
    for(int k=kh*Kh+lane;k<kh*Kh+Kh;k+=32){
        u64 x01,x23; lds2(x01,x23,aB+(u32)k*16u);
        u64 ww=pk2(W[k]);
        fma2(a01,ww,x01); fma2(a23,ww,x23);
    }
    #pragma unroll
    for(int o=16;o;o>>=1){ a01=add2(a01,__shfl_xor_sync(~0u,a01,o)); a23=add2(a23,__shfl_xor_sync(~0u,a23,o)); }
    if(!lane){ float* S=sm+OFF_STAG+w*4; unpk(a01,S[0],S[1]); unpk(a23,S[2],S[3]); }
    __syncthreads();
    if(tid<16){
        int nn=tid>>2,b=tid&3;
        float v=sm[OFF_STAG+nn*8+b]+sm[OFF_STAG+nn*8+4+b]+sm[offB+nn];
        if(relu)v=fmaxf(v,0.f);
        dd[(n0+nn)*4+b]=v;   // FIX: was dd[nn*4+b] — missing CTA neuron offset
    }
}

extern "C" __global__ void __launch_bounds__(NT,1) wavernn_kernel(
    const float* __restrict__ mel,   const float* __restrict__ aux,
    const float* __restrict__ WI,    const float* __restrict__ bI,
    const float* __restrict__ g1wih, const float* __restrict__ g1whh,
    const float* __restrict__ g1bih, const float* __restrict__ g1bhh,
    const float* __restrict__ g2wih, const float* __restrict__ g2whh,
    const float* __restrict__ g2bih, const float* __restrict__ g2bhh,
    const float* __restrict__ f1w,   const float* __restrict__ f1b,
    const float* __restrict__ f2w,   const float* __restrict__ f2b,
    const float* __restrict__ f3w,   const float* __restrict__ f3b,
    float* __restrict__ out)
{
    extern __shared__ float sm[];
    const int tid=threadIdx.x, bx=blockIdx.x, n0=bx*4;
    const u32 smb=(u32)__cvta_generic_to_shared(sm);
    u32 ep=ld_acq(&g_fl[bx*32]);   // own flag: race-free monotonic base

    // one-time: pre[t] = b_I + W_I[:,1:]*[mel,aux0] (numerics proven in R5)
    {
        int t0=bx*TT/G, t1=(bx+1)*TT/G;
        for(int p=0;p<4;p++){
            for(int i=tid;i<128*112;i+=NT){int j=i/112,c=i-j*112;sm[j*112+c]=__ldg(&WI[(p*128+j)*113+1+c]);}
            __syncthreads();
            int jl=tid>>1,bh=tid&1,j=p*128+jl;
            float bias=__ldg(&bI[j]);
            const float* Wr=sm+jl*112;
            for(int t=t0;t<t1;t++){
                float a0=bias,a1=bias;
                const float*m0=mel+((size_t)(bh*2)*TT+t)*80,*m1=mel+((size_t)(bh*2+1)*TT+t)*80;
                const float*x0=aux+((size_t)(bh*2)*TT+t)*128,*x1=aux+((size_t)(bh*2+1)*TT+t)*128;
                #pragma unroll 8
                for(int c=0;c<80;c++){float wv=Wr[c];a0=fmaf(wv,__ldg(m0+c),a0);a1=fmaf(wv,__ldg(m1+c),a1);}
                #pragma unroll 8
                for(int c=0;c<32;c++){float wv=Wr[80+c];a0=fmaf(wv,__ldg(x0+c),a0);a1=fmaf(wv,__ldg(x1+c),a1);}
                g_pre[((size_t)t*512+j)*4+bh*2]=a0; g_pre[((size_t)t*512+j)*4+bh*2+1]=a1;
            }
            __syncthreads();
        }
    }
    // weights into SMEM (round-3 proven layout)
    for(int i=tid;i<6144;i+=NT){int j=i/1536,r=i-j*1536,g=r>>9,k=r&511;
        sm[OFF_G1I+i]=__ldg(&g1wih[(g*512+n0+j)*512+k]);
        sm[OFF_G1H+i]=__ldg(&g1whh[(g*512+n0+j)*512+k]);
        sm[OFF_G2H+i]=__ldg(&g2whh[(g*512+n0+j)*512+k]);}
    for(int i=tid;i<6528;i+=NT){int j=i/1632,r=i-j*1632,g=r/544,k=r-g*544;
        sm[OFF_G2I+i]=__ldg(&g2wih[(g*512+n0+j)*544+k]);}
    for(int i=tid;i<2176;i+=NT){int j=i/544,k=i-j*544;
        sm[OFF_F1W+i]=__ldg(&f1w[(n0+j)*544+k]); sm[OFF_F2W+i]=__ldg(&f2w[(n0+j)*544+k]);}
    for(int i=tid;i<2048;i+=NT) sm[OFF_F3W+i]=__ldg(&f3w[(n0+(i>>9))*512+(i&511)]);
    for(int i=tid;i<512;i+=NT)  sm[OFF_W0+i]=__ldg(&WI[i*113]);
    if(tid<16){
        int nn=tid>>2,c=tid&3,n=n0+nn; float v1,v2;
        if(c==0){v1=g1bih[n]+g1bhh[n];v2=g2bih[n]+g2bhh[n];}
        else if(c==1){v1=g1bih[512+n]+g1bhh[512+n];v2=g2bih[512+n]+g2bhh[512+n];}
        else if(c==2){v1=g1bih[1024+n];v2=g2bih[1024+n];}
        else{v1=g1bhh[1024+n];v2=g2bhh[1024+n];}
        sm[OFF_G1B+tid]=v1; sm[OFF_G2B+tid]=v2;
        g_h1[0][(n0+nn)*4+c]=0.f; g_h2[0][(n0+nn)*4+c]=0.f;
    }
    if(tid<4){sm[OFF_F1B+tid]=f1b[n0+tid];sm[OFF_F2B+tid]=f2b[n0+tid];sm[OFF_F3B+tid]=f3b[n0+tid];sm[OFF_SAMP+tid]=0.f;}
    BAR();

    float* outL=out+4*TT;
    for(int t=0;t<TT;t++){
        const int p=t&1;
        // step top: sample known; prefetch pre/h1/h2/aux; build x locally (no barrier)
        float4 sv=*(const float4*)(sm+OFF_SAMP);
        const float4* gp=(const float4*)g_pre+((size_t)t*512+2*tid);
        float4 p0=__ldcg(gp), p1=__ldcg(gp+1);
        {
            float4* H1=(float4*)(sm+OFF_ACTH); float4* H2=(float4*)(sm+OFF_ACTH2);
            const float4* s1=(const float4*)g_h1[p]+2*tid;
            const float4* s2=(const float4*)g_h2[p]+2*tid;
            H1[2*tid]=__ldcg(s1); H1[2*tid+1]=__ldcg(s1+1);
            H2[2*tid]=__ldcg(s2); H2[2*tid+1]=__ldcg(s2+1);
        }
        if(tid<96){int seg=tid>>5,c=tid&31,col=(seg+1)*32+c;
            ((float4*)(sm+OFF_AUX))[seg*32+c]=make_float4(
                aux[((size_t)0*TT+t)*128+col],aux[((size_t)1*TT+t)*128+col],
                aux[((size_t)2*TT+t)*128+col],aux[((size_t)3*TT+t)*128+col]);}
        {
            float wa=sm[OFF_W0+2*tid], wb=sm[OFF_W0+2*tid+1];
            float4 x0,x1;
            x0.x=fmaf(wa,sv.x,p0.x);x0.y=fmaf(wa,sv.y,p0.y);x0.z=fmaf(wa,sv.z,p0.z);x0.w=fmaf(wa,sv.w,p0.w);
            x1.x=fmaf(wb,sv.x,p1.x);x1.y=fmaf(wb,sv.y,p1.y);x1.z=fmaf(wb,sv.z,p1.z);x1.w=fmaf(wb,sv.w,p1.w);
            float4* Aa=(float4*)(sm+OFF_ACTA); Aa[2*tid]=x0; Aa[2*tid+1]=x1;
        }
        __syncthreads();
        gru_stage(sm,smb,OFF_ACTH,OFF_G1I,OFF_G1H,OFF_G1B,512,n0,g_x2,g_h1[p^1]);
        BAR();
        // GRU2
        ldx(sm+OFF_ACTA,g_x2);
        if(tid<32) ((float4*)(sm+OFF_ACTA))[512+tid]=((const float4*)(sm+OFF_AUX))[tid];
        __syncthreads();
        gru_stage(sm,smb,OFF_ACTH2,OFF_G2I,OFF_G2H,OFF_G2B,544,n0,g_x3,g_h2[p^1]);
        BAR();
        // fc1
        ldx(sm+OFF_ACTA,g_x3);
        if(tid<32) ((float4*)(sm+OFF_ACTA))[512+tid]=((const float4*)(sm+OFF_AUX))[32+tid];
        __syncthreads();
        fc_stage(sm,smb,OFF_F1W,OFF_F1B,544,n0,g_y1,true);
        BAR();
        // fc2
        ldx(sm+OFF_ACTA,g_y1);
        if(tid<32) ((float4*)(sm+OFF_ACTA))[512+tid]=((const float4*)(sm+OFF_AUX))[64+tid];
        __syncthreads();
        fc_stage(sm,smb,OFF_F2W,OFF_F2B,544,n0,g_y2,true);
        BAR();
        // fc3 + argmax keys
        ldx(sm+OFF_ACTA,g_y2);
        __syncthreads();
        {
            const int w=tid>>5,lane=tid&31,n=w>>1,kh=w&1;
            const u32 aB=smb+(u32)OFF_ACTA*4u;
            const float* W=sm+OFF_F3W+n*512;
            u64 a01=0,a23=0;
            #pragma unroll 2
            for(int k=kh*256+lane;k<kh*256+256;k+=32){
                u64 x01,x23; lds2(x01,x23,aB+(u32)k*16u);
                u64 ww=pk2(W[k]);
                fma2(a01,ww,x01); fma2(a23,ww,x23);
            }
            #pragma unroll
            for(int o=16;o;o>>=1){ a01=add2(a01,__shfl_xor_sync(~0u,a01,o)); a23=add2(a23,__shfl_xor_sync(~0u,a23,o)); }
            if(!lane){ float* S=sm+OFF_STAG+w*4; unpk(a01,S[0],S[1]); unpk(a23,S[2],S[3]); }
            __syncthreads();
            if(tid<16){
                int nn=tid>>2,b=tid&3;
                float v=sm[OFF_STAG+nn*8+b]+sm[OFF_STAG+nn*8+4+b]+sm[OFF_F3B+nn];
                outL[((size_t)b*TT+t)*512+n0+nn]=v;
                u32 u=__float_as_uint(v); u=(u&0x80000000u)?~u:(u|0x80000000u);
                u64 key=((u64)u<<32)|(u32)(511-(n0+nn));
                u64 v1=__shfl_xor_sync(0xffffu,key,4); if(v1>key)key=v1;
                u64 v2=__shfl_xor_sync(0xffffu,key,8); if(v2>key)key=v2;
                if(tid<4) g_cand[bx*4+tid]=key;
            }
        }
        BAR();
        // argmax all-reduce: warp w = batch w
        if(tid<128){
            int w=tid>>5,lane=tid&31;
            u64 c=0ull;
            #pragma unroll
            for(int j=0;j<4;j++){ u64 v=__ldcg(&g_cand[(lane+32*j)*4+w]); if(v>c)c=v; }
            #pragma unroll
            for(int o=16;o;o>>=1){ u64 v=__shfl_xor_sync(~0u,c,o); if(v>c)c=v; }
            if(lane==0){
                int idx=511-(int)(c&0xffffffffull);
                float s=2.f*(float)idx/511.f-1.f;
                sm[OFF_SAMP+w]=s;
                if(bx==0) out[w*TT+t]=s;
            }
        }
        __syncthreads();
    }
}

extern "C" void kernel_launch(void* const* d_in, const int* in_sizes, int n_in,
                              void* d_out, int out_size){
    (void)in_sizes;(void)n_in;(void)out_size;
    cudaFuncSetAttribute(wavernn_kernel, cudaFuncAttributeMaxDynamicSharedMemorySize, SMEM_BYTES);
    wavernn_kernel<<<G,NT,SMEM_BYTES>>>(
        (const float*)d_in[0],(const float*)d_in[1],(const float*)d_in[2],
        (const float*)d_in[3],(const float*)d_in[4],(const float*)d_in[5],
        (const float*)d_in[6],(const float*)d_in[7],(const float*)d_in[8],
        (const float*)d_in[9],(const float*)d_in[10],(const float*)d_in[11],
        (const float*)d_in[12],(const float*)d_in[13],(const float*)d_in[14],
        (const float*)d_in[15],(const float*)d_in[16],(const float*)d_in[17],
        (float*)d_out);
}